// round 4
// baseline (speedup 1.0000x reference)
#include <cuda_runtime.h>

typedef unsigned long long u64;
typedef unsigned int u32;

#define IMG_W 2048
#define IMG_H 2048
#define NWORDS 32               // 32 x u64 = 2048 bits per column
#define NPIX (IMG_W * IMG_H)
#define COFF 8                  // column padding: prefetch never bounds-checks
#define NCOLS (IMG_W + 2 * COFF)

// Interleaved bit grids, column-major: elem (c, w) = {A, L} for 64 rows.
// d_AL: canonical row order. d_ALr: bit/word-reversed rows
// (d_ALr[c][w] = brevll(d_AL[c][31-w])).
__device__ ulonglong2 d_AL [NCOLS * NWORDS];
__device__ ulonglong2 d_ALr[NCOLS * NWORDS];

// ---------------------------------------------------------------------------
// Fused: low/high outputs + bitpack {A = thin>=3, L = thin>=1} in both
// orientations.
// ---------------------------------------------------------------------------
__global__ void k_prep(const float* __restrict__ thin, float* __restrict__ out) {
    int c = blockIdx.x * 32 + threadIdx.x;
    int w = blockIdx.y * blockDim.y + threadIdx.y;
    u64 L = 0, A = 0;
    size_t base = (size_t)(w * 64) * IMG_W + c;
    #pragma unroll 8
    for (int b = 0; b < 64; ++b) {
        size_t idx = base + (size_t)b * IMG_W;
        float v = thin[idx];
        bool lo = (v >= 1.0f), hi = (v >= 3.0f);
        out[idx]        = lo ? v : 0.0f;   // low
        out[NPIX + idx] = hi ? v : 0.0f;   // high
        L |= ((u64)lo) << b;
        A |= ((u64)hi) << b;
    }
    d_AL [(c + COFF) * NWORDS + w]            = make_ulonglong2(A, L);
    d_ALr[(c + COFF) * NWORDS + (31 - w)]     =
        make_ulonglong2(__brevll(A), __brevll(L));
}

// ---------------------------------------------------------------------------
// One directional trace pass, single warp. Lane k owns 64 virtual rows
// (virtual == stored orientation of ld grid; no brev on loads ever).
// Gated-or scan == carry chain of p+g (g subset p). HW carry flags give
// generate/propagate; cross-lane carries via 2 ballots + scalar 33-bit add.
// Full cin-speculation: only C->SEL->OR on the post-ballot chain.
// CROSS: store to the OTHER grid at word 31-lane with brevll.
// ---------------------------------------------------------------------------
template <bool XR, bool CROSS>
__device__ __forceinline__ void trace_pass(const int lane,
                                           const ulonglong2* __restrict__ ldb,
                                           u64* __restrict__ stb) {
    const u32 FULL = 0xffffffffu;
    u64 INTM = ~0ull;
    if (lane == 0)  INTM &= ~1ull;
    if (lane == 31) INTM &= 0x7fffffffffffffffull;
    const u32 notTop = (lane == 31) ? 0u : ~0u;

    const int dx = XR ? -1 : 1;
    const int cx0 = XR ? (IMG_W - 2) : 1;

    auto ld = [&](int c, u64& A, u64& L) {
        ulonglong2 v = ldb[(size_t)(c + COFF) * NWORDS];
        A = v.x; L = v.y;
    };
    auto st = [&](int c, u64 v) {
        stb[(size_t)(c + COFF) * NWORDS * 2] = CROSS ? __brevll(v) : v;
    };

    u64 Ap, Lp, Ac, Lc, An, Ln;
    ld(cx0 - dx, Ap, Lp);
    ld(cx0,      Ac, Lc);
    ld(cx0 + dx, An, Ln);
    u64 gc = Ac & INTM, pc = Lc & INTM;
    u64 AnM = An & INTM, LnM = Ln & INTM;
    u64 Ab[6], Lb[6];
    #pragma unroll
    for (int j = 0; j < 6; ++j) ld(cx0 + (2 + j) * dx, Ab[j], Lb[j]);

    int cx = cx0;
    #pragma unroll 1
    for (int blk = 0; blk < (IMG_W - 2) / 6; ++blk) {      // 341 x 6 = 2046
        #pragma unroll
        for (int j = 0; j < 6; ++j) {
            // ---- scan of column cx (g=gc, p=pc) ----
            u64 sum0, sum1; u32 cgen, cprop;
            asm("add.cc.u64 %0, %4, %5;\n\t"
                "addc.u32 %2, 0, 0;\n\t"
                "add.cc.u64 %1, %0, 1;\n\t"
                "addc.u32 %3, 0, 0;"
                : "=l"(sum0), "=l"(sum1), "=r"(cgen), "=r"(cprop)
                : "l"(pc), "l"(gc));
            u32 b0 = ((u32)gc & 1u) | (((u32)pc << 1) & 2u);
            u32 b0n = __shfl_down_sync(FULL, b0, 1) & notTop;
            u32 G = __ballot_sync(FULL, cgen);
            u32 P = __ballot_sync(FULL, cprop);
            // speculative carry-bit words and smears (off the ballot chain)
            u64 cb0 = sum0 ^ pc ^ gc;
            u64 cb1 = sum1 ^ pc ^ gc;
            u64 mid0 = cb0 | (cb0 >> 2), mid1 = cb1 | (cb1 >> 2);
            u64 side0 = mid0 | (cb0 >> 1), side1 = mid1 | (cb1 >> 1);
            // cross-lane carries
            u64 C = ((u64)P + (u64)G) ^ (u64)(P ^ G);
            u32 Cs = (u32)(C >> lane);            // bit0=cin, bit1=cout
            u32 cin = Cs & 1u;
            u32 co  = Cs & 2u;
            u32 s0n = (b0n & 1u) | ((b0n >> 1) & ((Cs >> 1) & 1u));
            u64 hi_mid  = ((u64)co << 61) | ((u64)s0n << 63);
            u64 hi_side = hi_mid | ((u64)co << 62);
            u64 mid  = (cin ? mid1  : mid0 ) | hi_mid;
            u64 side = (cin ? side1 : side0) | hi_side;

            st(cx - dx, Ap | (side & Lp));        // final for this pass
            Ap = Ac | (mid & Lc);  Lp = Lc;
            Ac = An | (side & Ln); Lc = Ln;
            gc = AnM | (side & LnM);              // critical recurrence
            pc = LnM;
            An = Ab[j]; Ln = Lb[j];
            AnM = An & INTM; LnM = Ln & INTM;
            ld(cx + 8 * dx, Ab[j], Lb[j]);        // padded: no bounds check
            cx += dx;
        }
    }
    st(cx - dx, Ap);
    st(cx, Ac);
}

__global__ void __launch_bounds__(32, 1) k_trace() {
    const int lane = threadIdx.x;
    // p1 FF: read AL,  write ALr (cross)
    trace_pass<false, true >(lane, d_AL  + lane, (u64*)(d_ALr + (31 - lane)));
    __threadfence_block(); __syncwarp();
    // p2 TT: read ALr, write ALr
    trace_pass<true,  false>(lane, d_ALr + lane, (u64*)(d_ALr + lane));
    __threadfence_block(); __syncwarp();
    // p3 FT: read ALr, write AL (cross)
    trace_pass<false, true >(lane, d_ALr + lane, (u64*)(d_AL  + (31 - lane)));
    __threadfence_block(); __syncwarp();
    // p4 TF: read AL,  write AL
    trace_pass<true,  false>(lane, d_AL  + lane, (u64*)(d_AL  + lane));
}

// ---------------------------------------------------------------------------
// final = A ? thin : 0. Tile 64 rows x 32 cols; thread owns one column-word,
// writes 8 coalesced pixels.
// ---------------------------------------------------------------------------
__global__ void k_final(const float* __restrict__ thin, float* __restrict__ out) {
    int c0 = blockIdx.x * 32;
    int r0 = blockIdx.y * 64;
    int lane = threadIdx.x & 31;
    int sub  = threadIdx.x >> 5;      // 0..7
    u64 wrd = d_AL[(c0 + lane + COFF) * NWORDS + (r0 >> 6)].x;
    #pragma unroll
    for (int k = 0; k < 8; ++k) {
        int rr = sub * 8 + k;
        size_t idx = (size_t)(r0 + rr) * IMG_W + c0 + lane;
        bool act = (wrd >> rr) & 1ull;
        out[2 * NPIX + idx] = act ? thin[idx] : 0.0f;
    }
}

// ---------------------------------------------------------------------------
extern "C" void kernel_launch(void* const* d_in, const int* in_sizes, int n_in,
                              void* d_out, int out_size) {
    const float* thin = (const float*)d_in[0];
    float* out = (float*)d_out;

    dim3 bpB(32, 8);
    dim3 bpG(IMG_W / 32, NWORDS / 8);
    k_prep<<<bpG, bpB>>>(thin, out);

    k_trace<<<1, 32>>>();

    dim3 fG(IMG_W / 32, IMG_H / 64);
    k_final<<<fG, 256>>>(thin, out);
}